// round 4
// baseline (speedup 1.0000x reference)
#include <cuda_runtime.h>
#include <cuda_fp16.h>
#include <cuda_bf16.h>
#include <cstdint>

// ---------------------------------------------------------------------------
// RGCN (3 layers, per-relation mean aggregation), GB300.
// Per layer:  out = [x | A_0..A_3] @ [root; W_0..W_3] + bias
//   where A_r = scatter_add(norm_r * x[src]) (mean via precomputed norm).
// GEMM runs in split-fp16 on tensor cores (mma.sync m16n8k16, fp32 accum):
//   A' = [A_hi | A_hi | A_lo],  B' = [B_hi; B_lo; B_hi]   (K = 3*3840 = 11520)
// giving hi*hi + hi*lo + lo*hi  ==> fp32-class accuracy.
// Edge index/type dtype (int32 vs int64) is DETECTED at runtime and decoded
// into flat int32 arrays before use.
// ---------------------------------------------------------------------------

#define N_NODES 20000
#define N_EDGES 100000
#define D 768
#define NUM_REL 4
#define KDIM (5 * D)          // 3840 columns of [x | A_0..A_3]
#define KITER_PER_PHASE 120   // 3840 / BK
#define GEMM_ITERS 360        // 3 phases

// ------------------------- device scratch ----------------------------------
__device__ float  g_acc[(size_t)NUM_REL * N_NODES * D];   // 245.8 MB scatter target
__device__ __half g_XAhi[(size_t)N_NODES * KDIM];         // 153.6 MB
__device__ __half g_XAlo[(size_t)N_NODES * KDIM];         // 153.6 MB
__device__ __half g_Bthi[3][(size_t)D * KDIM];            // 3 x 5.9 MB  (Bt[n][k])
__device__ __half g_Btlo[3][(size_t)D * KDIM];
__device__ float  g_y[(size_t)N_NODES * D];               // 61.4 MB layer output
__device__ float  g_norm[N_EDGES];
__device__ int    g_deg[NUM_REL * N_NODES];
__device__ int    g_src[N_EDGES];
__device__ int    g_dst[N_EDGES];
__device__ int    g_et [N_EDGES];
__device__ int    g_is64;

// --------------------- index dtype detection + decode ----------------------
// If edge_index is int64 (little-endian), odd int32 words are the high halves
// of values < 20000 -> all zero. If int32, odd words are ~U[0,20000): a run of
// 256 zeros is impossible in practice.
__global__ void detect_dtype_kernel(const int* __restrict__ ei_raw) {
    __shared__ int any_nonzero;
    if (threadIdx.x == 0) any_nonzero = 0;
    __syncthreads();
    // sample 256 odd words spread across the first 2*N_EDGES int32 words
    int i = threadIdx.x;                       // 0..255
    int w = 2 * (i * (N_EDGES / 256) + 1) + 1; // odd word indices, in-bounds
    if (ei_raw[w] != 0) atomicExch(&any_nonzero, 1);
    __syncthreads();
    if (threadIdx.x == 0) g_is64 = any_nonzero ? 0 : 1;
}

__global__ void decode_edges_kernel(const int* __restrict__ ei_raw,
                                    const int* __restrict__ et_raw) {
    int e = blockIdx.x * blockDim.x + threadIdx.x;
    if (e >= N_EDGES) return;
    if (g_is64) {
        g_src[e] = ei_raw[2 * e];
        g_dst[e] = ei_raw[2 * (N_EDGES + e)];
        g_et [e] = et_raw[2 * e];
    } else {
        g_src[e] = ei_raw[e];
        g_dst[e] = ei_raw[N_EDGES + e];
        g_et [e] = et_raw[e];
    }
}

// ------------------------- degree / norm -----------------------------------
__global__ void zero_deg_kernel() {
    int i = blockIdx.x * blockDim.x + threadIdx.x;
    if (i < NUM_REL * N_NODES) g_deg[i] = 0;
}

__global__ void count_deg_kernel() {
    int e = blockIdx.x * blockDim.x + threadIdx.x;
    if (e < N_EDGES)
        atomicAdd(&g_deg[g_et[e] * N_NODES + g_dst[e]], 1);
}

__global__ void calc_norm_kernel() {
    int e = blockIdx.x * blockDim.x + threadIdx.x;
    if (e < N_EDGES) {
        int d = g_deg[g_et[e] * N_NODES + g_dst[e]];
        g_norm[e] = 1.0f / (float)(d > 1 ? d : 1);
    }
}

// ------------------ weight stacking + fp16 split (Bt[n][k]) ----------------
// B (stacked [root; W0..W3], shape [3840 x 768]) transposed to Bt [768 n][3840 k].
__global__ void convert_weights_kernel(const float* __restrict__ root,
                                       const float* __restrict__ W,
                                       __half* __restrict__ bthi,
                                       __half* __restrict__ btlo)
{
    int idx = blockIdx.x * blockDim.x + threadIdx.x;      // KDIM * (D/8) threads
    if (idx >= KDIM * (D / 8)) return;
    int k  = idx / (D / 8);
    int n0 = (idx % (D / 8)) * 8;
    const float* src = (k < D) ? (root + (size_t)k * D + n0)
                               : (W + (size_t)(k - D) * D + n0);
    #pragma unroll
    for (int j = 0; j < 8; j++) {
        float v  = src[j];
        __half h = __float2half_rn(v);
        __half l = __float2half_rn(v - __half2float(h));
        bthi[(size_t)(n0 + j) * KDIM + k] = h;
        btlo[(size_t)(n0 + j) * KDIM + k] = l;
    }
}

// ------------------------- per-layer kernels -------------------------------
__global__ void zero_acc_kernel() {
    size_t i = (size_t)blockIdx.x * blockDim.x + threadIdx.x;
    size_t n4 = (size_t)NUM_REL * N_NODES * D / 4;
    if (i < n4) ((float4*)g_acc)[i] = make_float4(0.f, 0.f, 0.f, 0.f);
}

// g_acc[r][dst] += relu?(x[src]) * norm[e]; one block (192 thr) per edge.
__global__ void scatter_kernel(const float* __restrict__ x, int relu_in)
{
    int e   = blockIdx.x;
    int src = g_src[e];
    int dst = g_dst[e];
    int r   = g_et [e];
    float w = g_norm[e];

    const float4* xi = (const float4*)(x + (size_t)src * D);
    float4*       o  = (float4*)(g_acc + ((size_t)r * N_NODES + dst) * D);
    int t = threadIdx.x;              // 0..191
    float4 v = xi[t];
    if (relu_in) {
        v.x = fmaxf(v.x, 0.f); v.y = fmaxf(v.y, 0.f);
        v.z = fmaxf(v.z, 0.f); v.w = fmaxf(v.w, 0.f);
    }
    atomicAdd(&o[t], make_float4(v.x * w, v.y * w, v.z * w, v.w * w));
}

// Build XA hi/lo fp16 [N x 3840]: cols 0..767 = relu?(x), cols 768+ = g_acc.
__global__ void convert_xa_kernel(const float* __restrict__ x, int relu_in)
{
    int idx = blockIdx.x * blockDim.x + threadIdx.x;   // N * (KDIM/8) threads
    if (idx >= N_NODES * (KDIM / 8)) return;
    int row  = idx / (KDIM / 8);
    int col0 = (idx % (KDIM / 8)) * 8;

    const float* src;
    bool do_relu = false;
    if (col0 < D) {
        src = x + (size_t)row * D + col0;
        do_relu = (relu_in != 0);
    } else {
        int c  = col0 - D;
        int r  = c / D;
        int cr = c % D;
        src = g_acc + ((size_t)r * N_NODES + row) * D + cr;
    }

    __half hi[8], lo[8];
    #pragma unroll
    for (int j = 0; j < 8; j++) {
        float v = src[j];
        if (do_relu) v = fmaxf(v, 0.f);
        hi[j] = __float2half_rn(v);
        lo[j] = __float2half_rn(v - __half2float(hi[j]));
    }
    size_t o = (size_t)row * KDIM + col0;
    *(uint4*)&g_XAhi[o] = *(uint4*)hi;
    *(uint4*)&g_XAlo[o] = *(uint4*)lo;
}

// ---------------------------------------------------------------------------
// Split-fp16 tensor-core GEMM:  C[20000 x 768] = A'[20000 x 11520] @ B'[11520 x 768]
//  BM=128 BN=128 BK=32, 256 threads (8 warps, 2x4), warp tile 64x32.
//  cp.async 2-stage double buffer; ldmatrix + mma.sync m16n8k16.
// ---------------------------------------------------------------------------
#define BK 32
#define APAD 40                    // smem row stride in halves (32 + 8)
#define STAGE_HALVES (128 * APAD)  // 5120 halves = 10240 B per stage per array

__device__ __forceinline__ uint32_t smem_u32(const void* p) {
    return (uint32_t)__cvta_generic_to_shared(p);
}

__global__ void __launch_bounds__(256, 2) gemm_split_kernel(
    const __half* __restrict__ XAhi, const __half* __restrict__ XAlo,
    const __half* __restrict__ Bthi, const __half* __restrict__ Btlo,
    const float*  __restrict__ bias, float* __restrict__ C)
{
    __shared__ __half As[2][STAGE_HALVES];
    __shared__ __half Bs[2][STAGE_HALVES];

    const int tid  = threadIdx.x;
    const int lane = tid & 31;
    const int warp = tid >> 5;
    const int wm   = warp & 1;          // 2 warps along M  -> 64 rows each
    const int wn   = warp >> 1;         // 4 warps along N  -> 32 cols each
    const int bx   = blockIdx.x * 128;  // N offset
    const int by   = blockIdx.y * 128;  // M offset

    // ---- global->shared load mapping (2 x 16B per thread per tile) ----
    const int ldr = tid >> 2;           // 0..63
    const int ldc = tid & 3;            // 16B chunk within 32-half row
    const int ar0 = by + ldr,        ar1 = by + 64 + ldr;
    const int asz0 = (ar0 < N_NODES) ? 16 : 0;
    const int asz1 = (ar1 < N_NODES) ? 16 : 0;
    const size_t aoff0 = (size_t)min(ar0, N_NODES - 1) * KDIM + ldc * 8;
    const size_t aoff1 = (size_t)min(ar1, N_NODES - 1) * KDIM + ldc * 8;
    const size_t boff0 = (size_t)(bx + ldr) * KDIM + ldc * 8;
    const size_t boff1 = (size_t)(bx + 64 + ldr) * KDIM + ldc * 8;

    const uint32_t As_u = smem_u32(&As[0][0]);
    const uint32_t Bs_u = smem_u32(&Bs[0][0]);
    const uint32_t a_st = (ldr)      * (APAD * 2) + ldc * 16;   // dst bytes in stage
    const uint32_t a_st1= (64 + ldr) * (APAD * 2) + ldc * 16;

    // ---- ldmatrix lane address offsets (bytes within a stage) ----
    const int a_lm_row = lane & 15;
    const int a_lm_c   = (lane >> 4) * 8;                 // +halves
    uint32_t a_lm[4];
    #pragma unroll
    for (int mt = 0; mt < 4; mt++)
        a_lm[mt] = (uint32_t)((wm * 64 + mt * 16 + a_lm_row) * (APAD * 2) + a_lm_c * 2);

    const int b_lm_n = (lane & 7) + ((lane >> 4) & 1) * 8;
    const int b_lm_c = ((lane >> 3) & 1) * 8;             // +halves
    uint32_t b_lm[2];
    #pragma unroll
    for (int nt2 = 0; nt2 < 2; nt2++)
        b_lm[nt2] = (uint32_t)((wn * 32 + nt2 * 16 + b_lm_n) * (APAD * 2) + b_lm_c * 2);

    float acc[4][4][4];
    #pragma unroll
    for (int i = 0; i < 4; i++)
        #pragma unroll
        for (int j = 0; j < 4; j++)
            #pragma unroll
            for (int v = 0; v < 4; v++) acc[i][j][v] = 0.f;

    // ---- async tile loader ----
    auto issue = [&](int it, int s) {
        int ph = 0, klocal = it * BK;
        if (it >= 2 * KITER_PER_PHASE)      { ph = 2; klocal -= 2 * KITER_PER_PHASE * BK; }
        else if (it >= KITER_PER_PHASE)     { ph = 1; klocal -= KITER_PER_PHASE * BK; }
        const __half* Ap = (ph == 2) ? XAlo : XAhi;
        const __half* Bp = (ph == 1) ? Btlo : Bthi;

        uint32_t ad = As_u + (uint32_t)s * (STAGE_HALVES * 2);
        uint32_t bd = Bs_u + (uint32_t)s * (STAGE_HALVES * 2);
        const __half* ag0 = Ap + aoff0 + klocal;
        const __half* ag1 = Ap + aoff1 + klocal;
        const __half* bg0 = Bp + boff0 + klocal;
        const __half* bg1 = Bp + boff1 + klocal;
        asm volatile("cp.async.cg.shared.global [%0], [%1], 16, %2;\n" ::
                     "r"(ad + a_st),  "l"(ag0), "r"(asz0));
        asm volatile("cp.async.cg.shared.global [%0], [%1], 16, %2;\n" ::
                     "r"(ad + a_st1), "l"(ag1), "r"(asz1));
        asm volatile("cp.async.cg.shared.global [%0], [%1], 16;\n" ::
                     "r"(bd + a_st),  "l"(bg0));
        asm volatile("cp.async.cg.shared.global [%0], [%1], 16;\n" ::
                     "r"(bd + a_st1), "l"(bg1));
        asm volatile("cp.async.commit_group;\n");
    };

    issue(0, 0);
    issue(1, 1);

    for (int it = 0; it < GEMM_ITERS; it++) {
        const int s = it & 1;
        if (it + 1 < GEMM_ITERS) asm volatile("cp.async.wait_group 1;\n");
        else                     asm volatile("cp.async.wait_group 0;\n");
        __syncthreads();

        const uint32_t abase = As_u + (uint32_t)s * (STAGE_HALVES * 2);
        const uint32_t bbase = Bs_u + (uint32_t)s * (STAGE_HALVES * 2);

        #pragma unroll
        for (int ks = 0; ks < 2; ks++) {
            uint32_t a[4][4], b[4][2];
            #pragma unroll
            for (int mt = 0; mt < 4; mt++) {
                uint32_t addr = abase + a_lm[mt] + ks * 32;
                asm volatile("ldmatrix.sync.aligned.m8n8.x4.shared.b16 {%0,%1,%2,%3}, [%4];\n"
                             : "=r"(a[mt][0]), "=r"(a[mt][1]), "=r"(a[mt][2]), "=r"(a[mt][3])
                             : "r"(addr));
            }
            #pragma unroll
            for (int nt2 = 0; nt2 < 2; nt2++) {
                uint32_t addr = bbase + b_lm[nt2] + ks * 32;
                uint32_t r0, r1, r2, r3;
                asm volatile("ldmatrix.sync.aligned.m8n8.x4.shared.b16 {%0,%1,%2,%3}, [%4];\n"
                             : "=r"(r0), "=r"(r1), "=r"(r2), "=r"(r3) : "r"(addr));
                b[2 * nt2][0] = r0; b[2 * nt2][1] = r1;
                b[2 * nt2 + 1][0] = r2; b[2 * nt2 + 1][1] = r3;
            }
            #pragma unroll
            for (int mt = 0; mt < 4; mt++)
                #pragma unroll
                for (int nt = 0; nt < 4; nt++)
                    asm volatile(
                        "mma.sync.aligned.m16n8k16.row.col.f32.f16.f16.f32 "
                        "{%0,%1,%2,%3}, {%4,%5,%6,%7}, {%8,%9}, {%0,%1,%2,%3};\n"
                        : "+f"(acc[mt][nt][0]), "+f"(acc[mt][nt][1]),
                          "+f"(acc[mt][nt][2]), "+f"(acc[mt][nt][3])
                        : "r"(a[mt][0]), "r"(a[mt][1]), "r"(a[mt][2]), "r"(a[mt][3]),
                          "r"(b[nt][0]), "r"(b[nt][1]));
        }
        __syncthreads();
        if (it + 2 < GEMM_ITERS) issue(it + 2, s);
    }

    // ---- epilogue: fp32 + bias ----
    const int q  = lane >> 2;       // 0..7
    const int qc = (lane & 3) * 2;  // 0,2,4,6
    #pragma unroll
    for (int nt = 0; nt < 4; nt++) {
        int gcol = bx + wn * 32 + nt * 8 + qc;
        float b0 = bias[gcol], b1 = bias[gcol + 1];
        #pragma unroll
        for (int mt = 0; mt < 4; mt++) {
            int grow = by + wm * 64 + mt * 16 + q;
            if (grow < N_NODES) {
                C[(size_t)grow * D + gcol]     = acc[mt][nt][0] + b0;
                C[(size_t)grow * D + gcol + 1] = acc[mt][nt][1] + b1;
            }
            if (grow + 8 < N_NODES) {
                C[(size_t)(grow + 8) * D + gcol]     = acc[mt][nt][2] + b0;
                C[(size_t)(grow + 8) * D + gcol + 1] = acc[mt][nt][3] + b1;
            }
        }
    }
}

// ---------------------------------------------------------------------------
// Launch
// ---------------------------------------------------------------------------
extern "C" void kernel_launch(void* const* d_in, const int* in_sizes, int n_in,
                              void* d_out, int out_size)
{
    const float* entity = (const float*)d_in[0];
    const int*   ei_raw = (const int*)d_in[1];    // int32 OR int64 (detected)
    const int*   et_raw = (const int*)d_in[2];
    const float* W[3]    = {(const float*)d_in[3], (const float*)d_in[6], (const float*)d_in[9]};
    const float* root[3] = {(const float*)d_in[4], (const float*)d_in[7], (const float*)d_in[10]};
    const float* bias[3] = {(const float*)d_in[5], (const float*)d_in[8], (const float*)d_in[11]};

    __half *XAhi, *XAlo, *Bthi, *Btlo;
    float  *y;
    cudaGetSymbolAddress((void**)&XAhi, g_XAhi);
    cudaGetSymbolAddress((void**)&XAlo, g_XAlo);
    cudaGetSymbolAddress((void**)&Bthi, g_Bthi);
    cudaGetSymbolAddress((void**)&Btlo, g_Btlo);
    cudaGetSymbolAddress((void**)&y,    g_y);

    // Decode edges (dtype-robust), then norms (once per launch)
    detect_dtype_kernel<<<1, 256>>>(ei_raw);
    decode_edges_kernel<<<(N_EDGES + 255) / 256, 256>>>(ei_raw, et_raw);
    zero_deg_kernel<<<(NUM_REL * N_NODES + 255) / 256, 256>>>();
    count_deg_kernel<<<(N_EDGES + 255) / 256, 256>>>();
    calc_norm_kernel<<<(N_EDGES + 255) / 256, 256>>>();

    // Weight stacking + split (once per launch)
    int wthreads = KDIM * (D / 8);
    for (int L = 0; L < 3; L++)
        convert_weights_kernel<<<(wthreads + 255) / 256, 256>>>(
            root[L], W[L],
            Bthi + (size_t)L * D * KDIM, Btlo + (size_t)L * D * KDIM);

    const float* xin = entity;
    float* outb[3] = {y, y, (float*)d_out};
    size_t acc4 = (size_t)NUM_REL * N_NODES * D / 4;
    int xathreads = N_NODES * (KDIM / 8);
    dim3 ggrid(D / 128, (N_NODES + 127) / 128);   // (6, 157)

    for (int L = 0; L < 3; L++) {
        int relu_in = (L > 0) ? 1 : 0;
        zero_acc_kernel<<<(int)((acc4 + 255) / 256), 256>>>();
        scatter_kernel<<<N_EDGES, D / 4>>>(xin, relu_in);
        convert_xa_kernel<<<(xathreads + 255) / 256, 256>>>(xin, relu_in);
        gemm_split_kernel<<<ggrid, 256>>>(
            XAhi, XAlo,
            Bthi + (size_t)L * D * KDIM, Btlo + (size_t)L * D * KDIM,
            bias[L], outb[L]);
        xin = outb[L];
    }
}